// round 5
// baseline (speedup 1.0000x reference)
#include <cuda_runtime.h>
#include <cuda_bf16.h>
#include <cstdint>

// ---------------------------------------------------------------------------
// RoutedBitLinear: out[b,s,o] = sum_i x[b,s,i] * sign[o,i] * scale[o, i/128]
// scale[o,g] = sum_p routing[p] * profile_scales[p, o*32+g]
//
// Toolchain compiles PTX at compute_103 (no 'a' suffix) => tcgen05 illegal.
// Portable path: prep kernels bake tf32-rounded X and W = sign*scale into
// __device__ scratch; GEMM uses mma.sync.m16n8k8.tf32 + cp.async + ldmatrix.
// ---------------------------------------------------------------------------

#define M_DIM 8192
#define N_DIM 4096
#define K_DIM 4096
#define G_GROUPS 131072            // 4096 * 32
#define BM 128
#define BN 128
#define BK 32                      // 128 B per row-tile
#define NKT (K_DIM / BK)           // 128 k-tiles
#define A_BYTES (BM * BK * 4)      // 16 KB
#define B_BYTES (BN * BK * 4)      // 16 KB
#define STAGE_BYTES (A_BYTES + B_BYTES)
#define NSTAGE 3
#define SMEM_BYTES (NSTAGE * STAGE_BYTES)   // 96 KB
#define GEMM_THREADS 256

// Scratch (no cudaMalloc allowed)
__device__ float g_blend[G_GROUPS];
__device__ float g_X[M_DIM * K_DIM];     // 128 MB, tf32-rounded
__device__ float g_W[N_DIM * K_DIM];     // 64 MB, tf32(sign*scale)

// ---------------------------------------------------------------------------
// helpers
// ---------------------------------------------------------------------------
__device__ __forceinline__ uint32_t smem_u32(const void* p) {
    uint32_t a;
    asm("{ .reg .u64 t; cvta.to.shared.u64 t, %1; cvt.u32.u64 %0, t; }"
        : "=r"(a) : "l"(p));
    return a;
}

__device__ __forceinline__ float tf32r(float x) {
    uint32_t u;
    asm("cvt.rna.tf32.f32 %0, %1;" : "=r"(u) : "f"(x));
    return __uint_as_float(u);
}

__device__ __forceinline__ void cp_async16(uint32_t dst, const void* src) {
    asm volatile("cp.async.cg.shared.global [%0], [%1], 16;"
                 :: "r"(dst), "l"(src) : "memory");
}

__device__ __forceinline__ void ldsm_x4(uint32_t* r, uint32_t addr) {
    asm volatile("ldmatrix.sync.aligned.m8n8.x4.shared.b16 {%0,%1,%2,%3}, [%4];"
                 : "=r"(r[0]), "=r"(r[1]), "=r"(r[2]), "=r"(r[3]) : "r"(addr));
}

__device__ __forceinline__ void mma_tf32(float* c, const uint32_t* a, const uint32_t* b) {
    asm volatile(
        "mma.sync.aligned.m16n8k8.row.col.f32.tf32.tf32.f32 "
        "{%0,%1,%2,%3}, {%4,%5,%6,%7}, {%8,%9}, {%0,%1,%2,%3};"
        : "+f"(c[0]), "+f"(c[1]), "+f"(c[2]), "+f"(c[3])
        : "r"(a[0]), "r"(a[1]), "r"(a[2]), "r"(a[3]), "r"(b[0]), "r"(b[1]));
}

// ---------------------------------------------------------------------------
// Prep kernels
// ---------------------------------------------------------------------------
__global__ void blend_kernel(const float* __restrict__ psc,
                             const float* __restrict__ routing) {
    int g = blockIdx.x * 256 + threadIdx.x;
    float s = 0.f;
#pragma unroll
    for (int p = 0; p < 8; ++p) s += routing[p] * psc[p * G_GROUPS + g];
    g_blend[g] = s;
}

__global__ void convx_kernel(const float4* __restrict__ x) {
    int i = blockIdx.x * 256 + threadIdx.x;   // < M*K/4
    float4 v = x[i];
    v.x = tf32r(v.x); v.y = tf32r(v.y); v.z = tf32r(v.z); v.w = tf32r(v.w);
    reinterpret_cast<float4*>(g_X)[i] = v;
}

__global__ void buildw_kernel(const float4* __restrict__ signs) {
    int i = blockIdx.x * 256 + threadIdx.x;   // < N*K/4
    int col4 = i & 1023;                      // quad index within row (K/4)
    int o = i >> 10;
    int grp = col4 >> 5;                      // (col4*4)/128
    float sc = g_blend[o * 32 + grp];
    float4 s = signs[i];                      // exactly +-1.0f
    float4 w;
    w.x = tf32r(sc * s.x); w.y = tf32r(sc * s.y);
    w.z = tf32r(sc * s.z); w.w = tf32r(sc * s.w);
    reinterpret_cast<float4*>(g_W)[i] = w;
}

// ---------------------------------------------------------------------------
// GEMM: C[8192,4096] = g_X @ g_W^T  (tf32 via mma.sync, fp32 accum)
// SMEM rows are 128 B; swizzle: 16B-chunk index ^= (row & 7).
// ---------------------------------------------------------------------------
__device__ __forceinline__ void load_stage_async(int m0, int n0, int kt,
                                                 uint32_t sbase, int slot, int tid) {
    uint32_t sA = sbase + slot * STAGE_BYTES;
    uint32_t sB = sA + A_BYTES;
    const float* gA = g_X + (size_t)m0 * K_DIM + kt * BK;
    const float* gB = g_W + (size_t)n0 * K_DIM + kt * BK;
#pragma unroll
    for (int it = 0; it < 4; ++it) {          // A: 1024 x 16B chunks
        int c = tid + it * 256;
        int r = c >> 3, q = c & 7;
        uint32_t dst = sA + r * 128 + ((q ^ (r & 7)) << 4);
        cp_async16(dst, gA + (size_t)r * K_DIM + q * 4);
    }
#pragma unroll
    for (int it = 0; it < 4; ++it) {          // B: 1024 x 16B chunks
        int c = tid + it * 256;
        int r = c >> 3, q = c & 7;
        uint32_t dst = sB + r * 128 + ((q ^ (r & 7)) << 4);
        cp_async16(dst, gB + (size_t)r * K_DIM + q * 4);
    }
}

__global__ void __launch_bounds__(GEMM_THREADS, 2)
gemm_tf32(float* __restrict__ C) {
    extern __shared__ __align__(1024) char smem[];
    const int tid  = threadIdx.x;
    const int lane = tid & 31;
    const int warp = tid >> 5;
    const int wm   = warp & 1;                 // 2 warps over M
    const int wn   = warp >> 1;                // 4 warps over N
    const int m0 = blockIdx.y * BM;
    const int n0 = blockIdx.x * BN;
    const uint32_t sbase = smem_u32(smem);

    float c[4][4][4];                           // [mt][nt][frag]
#pragma unroll
    for (int i = 0; i < 4; ++i)
#pragma unroll
        for (int j = 0; j < 4; ++j)
#pragma unroll
            for (int q = 0; q < 4; ++q) c[i][j][q] = 0.f;

    // prologue: stages 0,1 in flight
    load_stage_async(m0, n0, 0, sbase, 0, tid);
    asm volatile("cp.async.commit_group;" ::: "memory");
    load_stage_async(m0, n0, 1, sbase, 1, tid);
    asm volatile("cp.async.commit_group;" ::: "memory");

    // precomputed per-thread fragment offsets (within a stage, ks=0, tile 0)
    const int arow = wm * 64 + (lane & 15);            // + mt*16
    const uint32_t acb0 = (uint32_t)((lane >> 4) << 4);  // 0 or 16
    const int q2 = lane >> 3;
    const int brow = wn * 32 + (lane & 7) + ((q2 >> 1) << 3);  // + p*16
    const uint32_t bcb0 = (uint32_t)((q2 & 1) << 4);

    for (int kt = 0; kt < NKT; ++kt) {
        const int slot = kt % NSTAGE;
        asm volatile("cp.async.wait_group 1;" ::: "memory");
        __syncthreads();
        if (kt + 2 < NKT)
            load_stage_async(m0, n0, kt + 2, sbase, (kt + 2) % NSTAGE, tid);
        asm volatile("cp.async.commit_group;" ::: "memory");

        const uint32_t sA = sbase + slot * STAGE_BYTES;
        const uint32_t sB = sA + A_BYTES;
#pragma unroll
        for (int ks = 0; ks < 4; ++ks) {
            uint32_t a[16], b[8];
#pragma unroll
            for (int mt = 0; mt < 4; ++mt) {
                int r = arow + mt * 16;
                uint32_t cb = ks * 32 + acb0;
                ldsm_x4(a + mt * 4, sA + r * 128 + (cb ^ ((uint32_t)(r & 7) << 4)));
            }
#pragma unroll
            for (int p = 0; p < 2; ++p) {
                int r = brow + p * 16;
                uint32_t cb = ks * 32 + bcb0;
                ldsm_x4(b + p * 4, sB + r * 128 + (cb ^ ((uint32_t)(r & 7) << 4)));
            }
#pragma unroll
            for (int mt = 0; mt < 4; ++mt)
#pragma unroll
                for (int nt = 0; nt < 4; ++nt)
                    mma_tf32(c[mt][nt], a + mt * 4,
                             b + (nt >> 1) * 4 + (nt & 1) * 2);
        }
        __syncthreads();
    }

    // epilogue: direct f32 stores (float2 per frag pair)
#pragma unroll
    for (int mt = 0; mt < 4; ++mt) {
        int row = m0 + wm * 64 + mt * 16 + (lane >> 2);
#pragma unroll
        for (int nt = 0; nt < 4; ++nt) {
            int col = n0 + wn * 32 + nt * 8 + (lane & 3) * 2;
            float2 v0 = make_float2(c[mt][nt][0], c[mt][nt][1]);
            float2 v1 = make_float2(c[mt][nt][2], c[mt][nt][3]);
            *reinterpret_cast<float2*>(C + (size_t)row * N_DIM + col) = v0;
            *reinterpret_cast<float2*>(C + (size_t)(row + 8) * N_DIM + col) = v1;
        }
    }
}

// ---------------------------------------------------------------------------
// launch
// ---------------------------------------------------------------------------
extern "C" void kernel_launch(void* const* d_in, const int* in_sizes, int n_in,
                              void* d_out, int out_size) {
    const float* x       = (const float*)d_in[0];  // [4,2048,4096]
    const float* signs   = (const float*)d_in[1];  // [4096,4096]
    const float* psc     = (const float*)d_in[2];  // [8,131072]
    const float* routing = (const float*)d_in[3];  // [8]
    float* out = (float*)d_out;                    // [8192,4096] f32

    blend_kernel<<<G_GROUPS / 256, 256>>>(psc, routing);
    convx_kernel<<<(M_DIM * K_DIM / 4) / 256, 256>>>((const float4*)x);
    buildw_kernel<<<(N_DIM * K_DIM / 4) / 256, 256>>>((const float4*)signs);

    cudaFuncSetAttribute(gemm_tf32, cudaFuncAttributeMaxDynamicSharedMemorySize,
                         SMEM_BYTES);
    dim3 grid(N_DIM / BN, M_DIM / BM);  // N fast -> W panel stays L2-resident
    gemm_tf32<<<grid, GEMM_THREADS, SMEM_BYTES>>>(out);
}